// round 2
// baseline (speedup 1.0000x reference)
#include <cuda_runtime.h>
#include <math.h>

#define NUM_CLASS 20
#define IGNORE 255
#define DD 256
#define HH 256
#define WW 32
#define SPATIAL (DD*HH*WW)   // 2,097,152
#define NBLOCKS (SPATIAL/256)

__device__ double g_num;        // zero-initialized at module load; reset by last block
__device__ double g_den;
__device__ unsigned g_bcount;

__device__ __forceinline__ float gval(int a, int b) {
    // sum_c |onehot(a) - onehot(b)| with onehot(IGNORE)=0
    if (a == b) return 0.0f;
    if (a == IGNORE || b == IGNORE) return 1.0f;
    return 2.0f;
}

// exp(x) for x <= 0 (post max-subtraction), FFMA+ALU only, no MUFU.
// 2^y with y = x*log2(e); r = rint(y), f = y-r in [-0.5,0.5];
// 2^f via degree-5 Taylor of exp(f*ln2); scale by 2^r via exponent add.
__device__ __forceinline__ float fast_exp_npos(float x) {
    const float L2E = 1.442695041f;
    float y = x * L2E;
    float r = rintf(y);
    float f = y - r;
    float p = 1.3333558e-3f;                 // ln2^5/120
    p = fmaf(p, f, 9.6181291e-3f);           // ln2^4/24
    p = fmaf(p, f, 5.5504109e-2f);           // ln2^3/6
    p = fmaf(p, f, 2.4022651e-1f);           // ln2^2/2
    p = fmaf(p, f, 6.9314718e-1f);           // ln2
    p = fmaf(p, f, 1.0f);
    int ir = (int)r;                         // ir <= 0, small magnitude (inputs ~N(0,1))
    return __int_as_float(__float_as_int(p) + (ir << 23));
}

__global__ void __launch_bounds__(256)
loss_kernel(const float* __restrict__ pred,
            const int*   __restrict__ tgt,
            const float* __restrict__ cw,
            float* __restrict__ out) {
    const int s = blockIdx.x * blockDim.x + threadIdx.x;

    const int t = __ldg(&tgt[s]);
    const bool valid = (t != IGNORE);
    const int tc = valid ? t : 0;

    // ---- log_softmax at class t: single pass over 20 channels ----
    float v[NUM_CLASS];
    #pragma unroll
    for (int c = 0; c < NUM_CLASS; c++) {
        v[c] = __ldg(&pred[c * SPATIAL + s]);
    }
    float m = v[0];
    #pragma unroll
    for (int c = 1; c < NUM_CLASS; c++) m = fmaxf(m, v[c]);
    float sum = 0.0f;
    #pragma unroll
    for (int c = 0; c < NUM_CLASS; c++) sum += fast_exp_npos(v[c] - m);
    const float logp_t = v[tc] - m - logf(sum);

    const float w = __ldg(&cw[tc]);
    const float loss = valid ? (-w * logp_t) : 0.0f;
    float den = valid ? w : 0.0f;

    // ---- LGA weight: pure label-neighbor function ----
    const int wq = s & (WW - 1);
    const int h  = (s >> 5) & (HH - 1);
    const int d  = s >> 13;

    float lga = 0.0f;
    // W axis (stride 1)
    {
        int a, b; float sc;
        if (wq == 0)            { a = t;                  b = __ldg(&tgt[s + 1]);  sc = 1.0f; }
        else if (wq == WW - 1)  { a = __ldg(&tgt[s - 1]); b = t;                   sc = 1.0f; }
        else                    { a = __ldg(&tgt[s - 1]); b = __ldg(&tgt[s + 1]);  sc = 0.5f; }
        lga += sc * gval(a, b);
    }
    // H axis (stride WW)
    {
        int a, b; float sc;
        if (h == 0)             { a = t;                   b = __ldg(&tgt[s + WW]); sc = 1.0f; }
        else if (h == HH - 1)   { a = __ldg(&tgt[s - WW]); b = t;                   sc = 1.0f; }
        else                    { a = __ldg(&tgt[s - WW]); b = __ldg(&tgt[s + WW]); sc = 0.5f; }
        lga += sc * gval(a, b);
    }
    // D axis (stride WW*HH)
    {
        const int sd = WW * HH;
        int a, b; float sc;
        if (d == 0)             { a = t;                   b = __ldg(&tgt[s + sd]); sc = 1.0f; }
        else if (d == DD - 1)   { a = __ldg(&tgt[s - sd]); b = t;                   sc = 1.0f; }
        else                    { a = __ldg(&tgt[s - sd]); b = __ldg(&tgt[s + sd]); sc = 0.5f; }
        lga += sc * gval(a, b);
    }

    float num = loss * (1.0f + lga);   // ALPHA=1, BETA=1

    // ---- reduction: warp shuffle -> shared -> global double atomics ----
    #pragma unroll
    for (int off = 16; off > 0; off >>= 1) {
        num += __shfl_down_sync(0xFFFFFFFFu, num, off);
        den += __shfl_down_sync(0xFFFFFFFFu, den, off);
    }

    __shared__ float s_num[8];
    __shared__ float s_den[8];
    const int lane = threadIdx.x & 31;
    const int wid  = threadIdx.x >> 5;
    if (lane == 0) { s_num[wid] = num; s_den[wid] = den; }
    __syncthreads();

    if (threadIdx.x == 0) {
        float bn = 0.0f, bd = 0.0f;
        #pragma unroll
        for (int i = 0; i < 8; i++) { bn += s_num[i]; bd += s_den[i]; }
        atomicAdd(&g_num, (double)bn);
        atomicAdd(&g_den, (double)bd);
        __threadfence();
        unsigned done = atomicAdd(&g_bcount, 1u);
        if (done == (unsigned)(gridDim.x - 1)) {
            // last block: all atomics visible; finalize + reset for next replay
            double n = atomicAdd(&g_num, 0.0);
            double dd2 = atomicAdd(&g_den, 0.0);
            out[0] = (float)(n / dd2);
            g_num = 0.0;
            g_den = 0.0;
            g_bcount = 0u;
        }
    }
}

extern "C" void kernel_launch(void* const* d_in, const int* in_sizes, int n_in,
                              void* d_out, int out_size) {
    const float* pred = (const float*)d_in[0];
    const int*   tgt  = (const int*)d_in[1];
    const float* cw   = (const float*)d_in[2];
    float* out = (float*)d_out;

    loss_kernel<<<NBLOCKS, 256>>>(pred, tgt, cw, out);
}